// round 13
// baseline (speedup 1.0000x reference)
#include <cuda_runtime.h>
#include <cuda_bf16.h>
#include <math.h>
#include <cstdint>

// Problem constants
#define B_SZ 4
#define C_SZ 2048
#define E_SZ 1024
#define H_SZ 16
#define D_SZ 64
#define HD   (H_SZ * D_SZ)     // 1024
#define F3   (3 * HD)          // 3072
#define M_SZ (B_SZ * C_SZ)     // 8192

typedef __nv_bfloat16 bf16;

// Pre-split scratch (bf16 hi/lo pairs)
__device__ bf16 g_xh[(size_t)M_SZ * E_SZ],  g_xl[(size_t)M_SZ * E_SZ];
__device__ bf16 g_wqh[(size_t)F3 * E_SZ],   g_wql[(size_t)F3 * E_SZ];
__device__ bf16 g_woh[(size_t)E_SZ * HD],   g_wol[(size_t)E_SZ * HD];
__device__ bf16 g_qh[(size_t)M_SZ * F3],    g_ql[(size_t)M_SZ * F3];
__device__ bf16 g_ah[(size_t)M_SZ * HD],    g_al[(size_t)M_SZ * HD];

// ---------------------------------------------------------------------------
// Helpers
// ---------------------------------------------------------------------------
__device__ __forceinline__ uint32_t smem_u32(const void* p) {
    uint32_t a;
    asm("{ .reg .u64 t; cvta.to.shared.u64 t, %1; cvt.u32.u64 %0, t; }"
        : "=r"(a) : "l"(p));
    return a;
}
#define CP_ASYNC16(dst, src) \
    asm volatile("cp.async.cg.shared.global [%0], [%1], 16;" \
        :: "r"(dst), "l"(src) : "memory")
#define CP_COMMIT() asm volatile("cp.async.commit_group;" ::: "memory")
#define CP_WAIT(n)  asm volatile("cp.async.wait_group %0;" :: "n"(n) : "memory")

__device__ __forceinline__ void mma_bf16(float* c, const uint32_t* a, const uint32_t* b) {
    asm volatile(
        "mma.sync.aligned.m16n8k16.row.col.f32.bf16.bf16.f32 "
        "{%0,%1,%2,%3}, {%4,%5,%6,%7}, {%8,%9}, {%0,%1,%2,%3};"
        : "+f"(c[0]), "+f"(c[1]), "+f"(c[2]), "+f"(c[3])
        : "r"(a[0]), "r"(a[1]), "r"(a[2]), "r"(a[3]), "r"(b[0]), "r"(b[1]));
}

__device__ __forceinline__ void ldsm4(uint32_t* r, uint32_t addr) {
    asm volatile("ldmatrix.sync.aligned.m8n8.x4.shared.b16 {%0,%1,%2,%3}, [%4];"
        : "=r"(r[0]), "=r"(r[1]), "=r"(r[2]), "=r"(r[3]) : "r"(addr));
}
__device__ __forceinline__ void ldsm4t(uint32_t* r, uint32_t addr) {
    asm volatile("ldmatrix.sync.aligned.m8n8.x4.trans.shared.b16 {%0,%1,%2,%3}, [%4];"
        : "=r"(r[0]), "=r"(r[1]), "=r"(r[2]), "=r"(r[3]) : "r"(addr));
}

__device__ __forceinline__ uint32_t pack_bf16(bf16 a, bf16 b) {
    uint16_t lo = __bfloat16_as_ushort(a), hi = __bfloat16_as_ushort(b);
    return ((uint32_t)hi << 16) | lo;
}
__device__ __forceinline__ void split2(float x, float y, uint32_t& hi, uint32_t& lo) {
    bf16 hx = __float2bfloat16(x), hy = __float2bfloat16(y);
    bf16 lx = __float2bfloat16(x - __bfloat162float(hx));
    bf16 ly = __float2bfloat16(y - __bfloat162float(hy));
    hi = pack_bf16(hx, hy);
    lo = pack_bf16(lx, ly);
}

// ---------------------------------------------------------------------------
// Elementwise fp32 -> (hi, lo) bf16 split
// ---------------------------------------------------------------------------
__global__ __launch_bounds__(256) void split_kernel(
    const float* __restrict__ in, bf16* __restrict__ hi, bf16* __restrict__ lo, int n4)
{
    int i = blockIdx.x * 256 + threadIdx.x;
    if (i >= n4) return;
    float4 v = *(const float4*)(in + (size_t)i * 4);
    uint32_t h0, l0, h1, l1;
    split2(v.x, v.y, h0, l0);
    split2(v.z, v.w, h1, l1);
    *(uint2*)(hi + (size_t)i * 4) = make_uint2(h0, h1);
    *(uint2*)(lo + (size_t)i * 4) = make_uint2(l0, l1);
}

// ---------------------------------------------------------------------------
// Split-bf16 GEMM (BM=BN=128, BK=32, 8 warps 4m x 2n) with A-fragment hoisting:
// all A ldmatrix loads for both ks-steps issue at iter top, overlapping their
// latency with the first B-load+mma groups.
// ---------------------------------------------------------------------------
#define SSTB 40
#define OPB (128 * SSTB)
#define BUFB (4 * OPB)
#define GEMM_SMEM (2 * BUFB * 2)

template <bool SPLIT_OUT>
__global__ __launch_bounds__(256, 2) void gemm_bf3_kernel(
    const bf16* __restrict__ Ahi_g, const bf16* __restrict__ Alo_g,
    const bf16* __restrict__ Bhi_g, const bf16* __restrict__ Blo_g,
    float* __restrict__ Cf, bf16* __restrict__ Chi, bf16* __restrict__ Clo,
    int M, int N, int K)
{
    extern __shared__ bf16 sm[];
    const uint32_t smb = smem_u32(sm);

    const int tid  = threadIdx.x;
    const int wid  = tid >> 5, lane = tid & 31;
    const int bm   = blockIdx.y * 128, bn = blockIdx.x * 128;
    const int wm   = (wid & 3) * 32;
    const int wn   = (wid >> 2) * 64;
    const int qr   = lane >> 2;
    const int qk   = lane & 3;

    const int t8 = lane >> 3, r8 = lane & 7;
    const int a_r = ((t8 & 1) << 3) + r8;
    const int a_c = (t8 >> 1) << 3;
    const int b_r = ((t8 >> 1) << 3) + r8;
    const int b_c = (t8 & 1) << 3;

    const int lr0 = tid >> 2;
    const int lq  = tid & 3;

    const bf16* gAh0 = Ahi_g + (size_t)(bm + lr0) * K + lq * 8;
    const bf16* gAl0 = Alo_g + (size_t)(bm + lr0) * K + lq * 8;
    const bf16* gBh0 = Bhi_g + (size_t)(bn + lr0) * K + lq * 8;
    const bf16* gBl0 = Blo_g + (size_t)(bn + lr0) * K + lq * 8;
    const size_t rstep = (size_t)64 * K;

    uint32_t sAh[2], sAl[2], sBh[2], sBl[2];
    #pragma unroll
    for (int b = 0; b < 2; b++) {
        const uint32_t base = smb + b * BUFB * 2;
        sAh[b] = base + (lr0 * SSTB + lq * 8) * 2;
        sAl[b] = sAh[b] + OPB * 2;
        sBh[b] = sAl[b] + OPB * 2;
        sBl[b] = sBh[b] + OPB * 2;
    }
    const uint32_t sstep = 64 * SSTB * 2;

    float acc[2][8][4];
    #pragma unroll
    for (int mt = 0; mt < 2; mt++)
        #pragma unroll
        for (int nt = 0; nt < 8; nt++)
            #pragma unroll
            for (int v = 0; v < 4; v++) acc[mt][nt][v] = 0.f;

    const int NT = K / 32;

    auto issue = [&](int kt, int s) {
        const int off = kt * 32;
        CP_ASYNC16(sAh[s], gAh0 + off);  CP_ASYNC16(sAh[s] + sstep, gAh0 + rstep + off);
        CP_ASYNC16(sAl[s], gAl0 + off);  CP_ASYNC16(sAl[s] + sstep, gAl0 + rstep + off);
        CP_ASYNC16(sBh[s], gBh0 + off);  CP_ASYNC16(sBh[s] + sstep, gBh0 + rstep + off);
        CP_ASYNC16(sBl[s], gBl0 + off);  CP_ASYNC16(sBl[s] + sstep, gBl0 + rstep + off);
        CP_COMMIT();
    };

    issue(0, 0);

    for (int kt = 0; kt < NT; kt++) {
        CP_WAIT(0);
        __syncthreads();   // publishes tile kt; certifies compute kt-1 done

        if (kt + 1 < NT) issue(kt + 1, (kt + 1) & 1);

        const int buf = kt & 1;
        const uint32_t bAh = smb + buf * BUFB * 2;
        const uint32_t bAl = bAh + OPB * 2;
        const uint32_t bBh = bAl + OPB * 2;
        const uint32_t bBl = bBh + OPB * 2;

        // hoisted A fragments for BOTH ks-steps (8 ldsm4, 32 regs)
        uint32_t afh[2][2][4], afl[2][2][4];   // [ks][mt][4]
        #pragma unroll
        for (int ks = 0; ks < 2; ks++)
            #pragma unroll
            for (int mt = 0; mt < 2; mt++) {
                const uint32_t aoff =
                    ((wm + mt * 16 + a_r) * SSTB + ks * 16 + a_c) * 2;
                ldsm4(afh[ks][mt], bAh + aoff);
                ldsm4(afl[ks][mt], bAl + aoff);
            }

        #pragma unroll
        for (int ks = 0; ks < 2; ks++) {
            const int k0 = ks * 16;
            #pragma unroll
            for (int p = 0; p < 4; p++) {
                const uint32_t boff = ((wn + p * 16 + b_r) * SSTB + k0 + b_c) * 2;
                uint32_t bh4[4], bl4[4];
                ldsm4(bh4, bBh + boff);
                ldsm4(bl4, bBl + boff);
                #pragma unroll
                for (int mt = 0; mt < 2; mt++) {
                    mma_bf16(acc[mt][2 * p],     afh[ks][mt], bh4);
                    mma_bf16(acc[mt][2 * p + 1], afh[ks][mt], bh4 + 2);
                }
                #pragma unroll
                for (int mt = 0; mt < 2; mt++) {
                    mma_bf16(acc[mt][2 * p],     afh[ks][mt], bl4);
                    mma_bf16(acc[mt][2 * p + 1], afh[ks][mt], bl4 + 2);
                }
                #pragma unroll
                for (int mt = 0; mt < 2; mt++) {
                    mma_bf16(acc[mt][2 * p],     afl[ks][mt], bh4);
                    mma_bf16(acc[mt][2 * p + 1], afl[ks][mt], bh4 + 2);
                }
            }
        }
    }

    #pragma unroll
    for (int mt = 0; mt < 2; mt++) {
        const int r = bm + wm + mt * 16 + qr;
        #pragma unroll
        for (int nt = 0; nt < 8; nt++) {
            const int ncol = bn + wn + nt * 8 + 2 * qk;
            if (SPLIT_OUT) {
                uint32_t h, l;
                split2(acc[mt][nt][0], acc[mt][nt][1], h, l);
                *(uint32_t*)(Chi + (size_t)r * N + ncol) = h;
                *(uint32_t*)(Clo + (size_t)r * N + ncol) = l;
                split2(acc[mt][nt][2], acc[mt][nt][3], h, l);
                *(uint32_t*)(Chi + (size_t)(r + 8) * N + ncol) = h;
                *(uint32_t*)(Clo + (size_t)(r + 8) * N + ncol) = l;
            } else {
                *(float2*)(Cf + (size_t)r * N + ncol) =
                    make_float2(acc[mt][nt][0], acc[mt][nt][1]);
                *(float2*)(Cf + (size_t)(r + 8) * N + ncol) =
                    make_float2(acc[mt][nt][2], acc[mt][nt][3]);
            }
        }
    }
}

// ---------------------------------------------------------------------------
// Flash attention (exactly R8): double-buffered, 1 barrier/tile, LPT grid.
// ---------------------------------------------------------------------------
#define AST 72
#define ATILE (64 * AST)
#define ASTAGE (4 * ATILE)
#define ATTN_SMEM (2 * ASTAGE * 2)

__global__ __launch_bounds__(256) void attn_mma_kernel(
    const bf16* __restrict__ qh, const bf16* __restrict__ ql,
    bf16* __restrict__ ah, bf16* __restrict__ al)
{
    extern __shared__ bf16 asmem[];
    const uint32_t smb = smem_u32(asmem);

    const int tid = threadIdx.x, wid = tid >> 5, lane = tid & 31;
    const int qr = lane >> 2, qk = lane & 3;
    const int qb = (int)gridDim.y - 1 - (int)blockIdx.y;
    const int bh = blockIdx.x;
    const int b = bh >> 4, h = bh & 15;

    const size_t seq0 = (size_t)b * C_SZ;
    const int wr = qb * 128 + wid * 16;

    const int t8 = lane >> 3, r8 = lane & 7;
    const int kb_r = ((t8 >> 1) << 3) + r8;
    const int kb_c = (t8 & 1) << 3;
    const int vb_r = ((t8 & 1) << 3) + r8;
    const int vb_c = (t8 >> 1) << 3;

    const int kr0 = tid >> 3;
    const int kq  = tid & 7;
    const uint32_t lsoff = (kr0 * AST + kq * 8) * 2;
    const uint32_t kstep = 32 * AST * 2;

    uint32_t qhi[4][4], qlo[4][4];
    {
        const bf16* qb0 = qh + (seq0 + wr) * F3 + h * D_SZ;
        const bf16* qb1 = ql + (seq0 + wr) * F3 + h * D_SZ;
        #pragma unroll
        for (int kc = 0; kc < 4; kc++) {
            const int d0 = kc * 16 + 2 * qk;
            qhi[kc][0] = *(const uint32_t*)(qb0 + (size_t)qr * F3 + d0);
            qhi[kc][1] = *(const uint32_t*)(qb0 + (size_t)(qr + 8) * F3 + d0);
            qhi[kc][2] = *(const uint32_t*)(qb0 + (size_t)qr * F3 + d0 + 8);
            qhi[kc][3] = *(const uint32_t*)(qb0 + (size_t)(qr + 8) * F3 + d0 + 8);
            qlo[kc][0] = *(const uint32_t*)(qb1 + (size_t)qr * F3 + d0);
            qlo[kc][1] = *(const uint32_t*)(qb1 + (size_t)(qr + 8) * F3 + d0);
            qlo[kc][2] = *(const uint32_t*)(qb1 + (size_t)qr * F3 + d0 + 8);
            qlo[kc][3] = *(const uint32_t*)(qb1 + (size_t)(qr + 8) * F3 + d0 + 8);
        }
    }

    float m0 = -1e30f, m1 = -1e30f, l0 = 0.f, l1 = 0.f;
    float o[8][4];
    #pragma unroll
    for (int nt = 0; nt < 8; nt++)
        #pragma unroll
        for (int v = 0; v < 4; v++) o[nt][v] = 0.f;

    const int nkv = 2 * qb + 2;

    auto issue_tile = [&](int kb, int s) {
        const uint32_t sb = smb + s * ASTAGE * 2;
        const uint32_t uKh = sb,                 uKl = sb + ATILE * 2;
        const uint32_t uVh = sb + 2 * ATILE * 2, uVl = sb + 3 * ATILE * 2;
        const size_t krow0 = (seq0 + kb * 64 + kr0) * F3;
        const size_t kr32 = (size_t)32 * F3;
        const bf16* gKh = qh + krow0 + HD + h * D_SZ + kq * 8;
        const bf16* gKl = ql + krow0 + HD + h * D_SZ + kq * 8;
        const bf16* gVh = qh + krow0 + 2 * HD + h * D_SZ + kq * 8;
        const bf16* gVl = ql + krow0 + 2 * HD + h * D_SZ + kq * 8;
        CP_ASYNC16(uKh + lsoff, gKh);  CP_ASYNC16(uKh + lsoff + kstep, gKh + kr32);
        CP_ASYNC16(uKl + lsoff, gKl);  CP_ASYNC16(uKl + lsoff + kstep, gKl + kr32);
        CP_ASYNC16(uVh + lsoff, gVh);  CP_ASYNC16(uVh + lsoff + kstep, gVh + kr32);
        CP_ASYNC16(uVl + lsoff, gVl);  CP_ASYNC16(uVl + lsoff + kstep, gVl + kr32);
        CP_COMMIT();
    };

    issue_tile(0, 0);

    for (int kb = 0; kb < nkv; kb++) {
        CP_WAIT(0);
        __syncthreads();

        if (kb + 1 < nkv) issue_tile(kb + 1, (kb + 1) & 1);

        if (kb * 64 <= wr + 15) {
            const uint32_t sb = smb + (kb & 1) * ASTAGE * 2;
            const uint32_t uKhi = sb,                 uKlo = sb + ATILE * 2;
            const uint32_t uVhi = sb + 2 * ATILE * 2, uVlo = sb + 3 * ATILE * 2;

            float s[8][4];
            #pragma unroll
            for (int nt = 0; nt < 8; nt++)
                #pragma unroll
                for (int v = 0; v < 4; v++) s[nt][v] = 0.f;

            #pragma unroll
            for (int kc = 0; kc < 4; kc++) {
                const int k0 = kc * 16;
                #pragma unroll
                for (int p = 0; p < 4; p++) {
                    const uint32_t boff = ((p * 16 + kb_r) * AST + k0 + kb_c) * 2;
                    uint32_t bh4[4], bl4[4];
                    ldsm4(bh4, uKhi + boff);
                    ldsm4(bl4, uKlo + boff);
                    mma_bf16(s[2 * p],     qhi[kc], bh4);
                    mma_bf16(s[2 * p + 1], qhi[kc], bh4 + 2);
                    mma_bf16(s[2 * p],     qhi[kc], bl4);
                    mma_bf16(s[2 * p + 1], qhi[kc], bl4 + 2);
                    mma_bf16(s[2 * p],     qlo[kc], bh4);
                    mma_bf16(s[2 * p + 1], qlo[kc], bh4 + 2);
                }
            }

            const bool edge = (kb * 64 + 63 > wr);
            #pragma unroll
            for (int nt = 0; nt < 8; nt++) {
                #pragma unroll
                for (int v = 0; v < 4; v++) s[nt][v] *= 0.125f;
                if (edge) {
                    const int colb = kb * 64 + nt * 8 + 2 * qk;
                    const int r0 = wr + qr, r1 = r0 + 8;
                    if (colb > r0)     s[nt][0] = -1e30f;
                    if (colb + 1 > r0) s[nt][1] = -1e30f;
                    if (colb > r1)     s[nt][2] = -1e30f;
                    if (colb + 1 > r1) s[nt][3] = -1e30f;
                }
            }

            {
                float mx0 = -1e30f, mx1 = -1e30f;
                #pragma unroll
                for (int nt = 0; nt < 8; nt++) {
                    mx0 = fmaxf(mx0, fmaxf(s[nt][0], s[nt][1]));
                    mx1 = fmaxf(mx1, fmaxf(s[nt][2], s[nt][3]));
                }
                mx0 = fmaxf(mx0, __shfl_xor_sync(0xffffffffu, mx0, 1));
                mx0 = fmaxf(mx0, __shfl_xor_sync(0xffffffffu, mx0, 2));
                mx1 = fmaxf(mx1, __shfl_xor_sync(0xffffffffu, mx1, 1));
                mx1 = fmaxf(mx1, __shfl_xor_sync(0xffffffffu, mx1, 2));

                const float mn0 = fmaxf(m0, mx0), mn1 = fmaxf(m1, mx1);
                const float a0 = __expf(m0 - mn0), a1 = __expf(m1 - mn1);
                float s0 = 0.f, s1 = 0.f;
                #pragma unroll
                for (int nt = 0; nt < 8; nt++) {
                    s[nt][0] = __expf(s[nt][0] - mn0);
                    s[nt][1] = __expf(s[nt][1] - mn0);
                    s[nt][2] = __expf(s[nt][2] - mn1);
                    s[nt][3] = __expf(s[nt][3] - mn1);
                    s0 += s[nt][0] + s[nt][1];
                    s1 += s[nt][2] + s[nt][3];
                }
                s0 += __shfl_xor_sync(0xffffffffu, s0, 1);
                s0 += __shfl_xor_sync(0xffffffffu, s0, 2);
                s1 += __shfl_xor_sync(0xffffffffu, s1, 1);
                s1 += __shfl_xor_sync(0xffffffffu, s1, 2);
                l0 = l0 * a0 + s0;  m0 = mn0;
                l1 = l1 * a1 + s1;  m1 = mn1;
                #pragma unroll
                for (int nt = 0; nt < 8; nt++) {
                    o[nt][0] *= a0; o[nt][1] *= a0;
                    o[nt][2] *= a1; o[nt][3] *= a1;
                }
            }

            #pragma unroll
            for (int kc = 0; kc < 4; kc++) {
                uint32_t ph[4], pl[4];
                split2(s[2 * kc][0],     s[2 * kc][1],     ph[0], pl[0]);
                split2(s[2 * kc][2],     s[2 * kc][3],     ph[1], pl[1]);
                split2(s[2 * kc + 1][0], s[2 * kc + 1][1], ph[2], pl[2]);
                split2(s[2 * kc + 1][2], s[2 * kc + 1][3], ph[3], pl[3]);
                #pragma unroll
                for (int p = 0; p < 4; p++) {
                    const uint32_t voff = ((kc * 16 + vb_r) * AST + p * 16 + vb_c) * 2;
                    uint32_t bh4[4], bl4[4];
                    ldsm4t(bh4, uVhi + voff);
                    ldsm4t(bl4, uVlo + voff);
                    mma_bf16(o[2 * p],     ph, bh4);
                    mma_bf16(o[2 * p + 1], ph, bh4 + 2);
                    mma_bf16(o[2 * p],     ph, bl4);
                    mma_bf16(o[2 * p + 1], ph, bl4 + 2);
                    mma_bf16(o[2 * p],     pl, bh4);
                    mma_bf16(o[2 * p + 1], pl, bh4 + 2);
                }
            }
        }
    }

    const float i0 = 1.f / l0, i1 = 1.f / l1;
    #pragma unroll
    for (int nt = 0; nt < 8; nt++) {
        const int col = h * D_SZ + nt * 8 + 2 * qk;
        const size_t r0 = seq0 + wr + qr, r1 = r0 + 8;
        uint32_t hh, ll;
        split2(o[nt][0] * i0, o[nt][1] * i0, hh, ll);
        *(uint32_t*)(ah + r0 * HD + col) = hh;
        *(uint32_t*)(al + r0 * HD + col) = ll;
        split2(o[nt][2] * i1, o[nt][3] * i1, hh, ll);
        *(uint32_t*)(ah + r1 * HD + col) = hh;
        *(uint32_t*)(al + r1 * HD + col) = ll;
    }
}

// ---------------------------------------------------------------------------
extern "C" void kernel_launch(void* const* d_in, const int* in_sizes, int n_in,
                              void* d_out, int out_size)
{
    const float* x     = (const float*)d_in[0];
    const float* w_qkv = (const float*)d_in[1];
    const float* w_out = (const float*)d_in[2];
    float* out = (float*)d_out;

    bf16 *xh, *xl, *wqh, *wql, *woh, *wol, *qh, *ql, *ahp, *alp;
    cudaGetSymbolAddress((void**)&xh,  g_xh);  cudaGetSymbolAddress((void**)&xl,  g_xl);
    cudaGetSymbolAddress((void**)&wqh, g_wqh); cudaGetSymbolAddress((void**)&wql, g_wql);
    cudaGetSymbolAddress((void**)&woh, g_woh); cudaGetSymbolAddress((void**)&wol, g_wol);
    cudaGetSymbolAddress((void**)&qh,  g_qh);  cudaGetSymbolAddress((void**)&ql,  g_ql);
    cudaGetSymbolAddress((void**)&ahp, g_ah);  cudaGetSymbolAddress((void**)&alp, g_al);

    cudaFuncSetAttribute(gemm_bf3_kernel<true>,
                         cudaFuncAttributeMaxDynamicSharedMemorySize, GEMM_SMEM);
    cudaFuncSetAttribute(gemm_bf3_kernel<false>,
                         cudaFuncAttributeMaxDynamicSharedMemorySize, GEMM_SMEM);
    cudaFuncSetAttribute(attn_mma_kernel,
                         cudaFuncAttributeMaxDynamicSharedMemorySize, ATTN_SMEM);

    // 0) split inputs once
    {
        int n4 = (M_SZ * E_SZ) / 4;
        split_kernel<<<(n4 + 255) / 256, 256>>>(x, xh, xl, n4);
        n4 = (F3 * E_SZ) / 4;
        split_kernel<<<(n4 + 255) / 256, 256>>>(w_qkv, wqh, wql, n4);
        n4 = (E_SZ * HD) / 4;
        split_kernel<<<(n4 + 255) / 256, 256>>>(w_out, woh, wol, n4);
    }

    // 1) QKV projection -> split bf16 qkv
    {
        dim3 grid(F3 / 128, M_SZ / 128);
        gemm_bf3_kernel<true><<<grid, 256, GEMM_SMEM>>>(
            xh, xl, wqh, wql, nullptr, qh, ql, M_SZ, F3, E_SZ);
    }

    // 2) causal flash attention -> split bf16 attn
    {
        dim3 grid(B_SZ * H_SZ, C_SZ / 128);
        attn_mma_kernel<<<grid, 256, ATTN_SMEM>>>(qh, ql, ahp, alp);
    }

    // 3) output projection -> fp32 out
    {
        dim3 grid(E_SZ / 128, M_SZ / 128);
        gemm_bf3_kernel<false><<<grid, 256, GEMM_SMEM>>>(
            ahp, alp, woh, wol, out, nullptr, nullptr, M_SZ, E_SZ, HD);
    }
}

// round 14
// speedup vs baseline: 1.6113x; 1.6113x over previous
#include <cuda_runtime.h>
#include <cuda_bf16.h>
#include <math.h>
#include <cstdint>

// Problem constants
#define B_SZ 4
#define C_SZ 2048
#define E_SZ 1024
#define H_SZ 16
#define D_SZ 64
#define HD   (H_SZ * D_SZ)     // 1024
#define F3   (3 * HD)          // 3072
#define M_SZ (B_SZ * C_SZ)     // 8192

typedef __nv_bfloat16 bf16;

// Pre-split scratch (bf16 hi/lo pairs)
__device__ bf16 g_xh[(size_t)M_SZ * E_SZ],  g_xl[(size_t)M_SZ * E_SZ];
__device__ bf16 g_wqh[(size_t)F3 * E_SZ],   g_wql[(size_t)F3 * E_SZ];
__device__ bf16 g_woh[(size_t)E_SZ * HD],   g_wol[(size_t)E_SZ * HD];
__device__ bf16 g_qh[(size_t)M_SZ * F3],    g_ql[(size_t)M_SZ * F3];
__device__ bf16 g_ah[(size_t)M_SZ * HD],    g_al[(size_t)M_SZ * HD];

// ---------------------------------------------------------------------------
// Helpers
// ---------------------------------------------------------------------------
__device__ __forceinline__ uint32_t smem_u32(const void* p) {
    uint32_t a;
    asm("{ .reg .u64 t; cvta.to.shared.u64 t, %1; cvt.u32.u64 %0, t; }"
        : "=r"(a) : "l"(p));
    return a;
}
#define CP_ASYNC16(dst, src) \
    asm volatile("cp.async.cg.shared.global [%0], [%1], 16;" \
        :: "r"(dst), "l"(src) : "memory")
#define CP_COMMIT() asm volatile("cp.async.commit_group;" ::: "memory")
#define CP_WAIT(n)  asm volatile("cp.async.wait_group %0;" :: "n"(n) : "memory")

__device__ __forceinline__ void mma_bf16(float* c, const uint32_t* a, const uint32_t* b) {
    asm volatile(
        "mma.sync.aligned.m16n8k16.row.col.f32.bf16.bf16.f32 "
        "{%0,%1,%2,%3}, {%4,%5,%6,%7}, {%8,%9}, {%0,%1,%2,%3};"
        : "+f"(c[0]), "+f"(c[1]), "+f"(c[2]), "+f"(c[3])
        : "r"(a[0]), "r"(a[1]), "r"(a[2]), "r"(a[3]), "r"(b[0]), "r"(b[1]));
}

__device__ __forceinline__ void ldsm4(uint32_t* r, uint32_t addr) {
    asm volatile("ldmatrix.sync.aligned.m8n8.x4.shared.b16 {%0,%1,%2,%3}, [%4];"
        : "=r"(r[0]), "=r"(r[1]), "=r"(r[2]), "=r"(r[3]) : "r"(addr));
}
__device__ __forceinline__ void ldsm4t(uint32_t* r, uint32_t addr) {
    asm volatile("ldmatrix.sync.aligned.m8n8.x4.trans.shared.b16 {%0,%1,%2,%3}, [%4];"
        : "=r"(r[0]), "=r"(r[1]), "=r"(r[2]), "=r"(r[3]) : "r"(addr));
}

__device__ __forceinline__ uint32_t pack_bf16(bf16 a, bf16 b) {
    uint16_t lo = __bfloat16_as_ushort(a), hi = __bfloat16_as_ushort(b);
    return ((uint32_t)hi << 16) | lo;
}
__device__ __forceinline__ void split2(float x, float y, uint32_t& hi, uint32_t& lo) {
    bf16 hx = __float2bfloat16(x), hy = __float2bfloat16(y);
    bf16 lx = __float2bfloat16(x - __bfloat162float(hx));
    bf16 ly = __float2bfloat16(y - __bfloat162float(hy));
    hi = pack_bf16(hx, hy);
    lo = pack_bf16(lx, ly);
}

// ---------------------------------------------------------------------------
// Elementwise fp32 -> (hi, lo) bf16 split
// ---------------------------------------------------------------------------
__global__ __launch_bounds__(256) void split_kernel(
    const float* __restrict__ in, bf16* __restrict__ hi, bf16* __restrict__ lo, int n4)
{
    int i = blockIdx.x * 256 + threadIdx.x;
    if (i >= n4) return;
    float4 v = *(const float4*)(in + (size_t)i * 4);
    uint32_t h0, l0, h1, l1;
    split2(v.x, v.y, h0, l0);
    split2(v.z, v.w, h1, l1);
    *(uint2*)(hi + (size_t)i * 4) = make_uint2(h0, h1);
    *(uint2*)(lo + (size_t)i * 4) = make_uint2(l0, l1);
}

// ---------------------------------------------------------------------------
// Split-bf16 GEMM (exact R8 structure: two barriers/iter, no hoisting).
// QSCALE: multiply Q-range columns (ncol < HD) by 0.125 in the epilogue
// (exact power-of-2; folds attention's 1/sqrt(D) into the QKV output).
// ---------------------------------------------------------------------------
#define SSTB 40
#define OPB (128 * SSTB)
#define BUFB (4 * OPB)
#define GEMM_SMEM (2 * BUFB * 2)

template <bool SPLIT_OUT, bool QSCALE>
__global__ __launch_bounds__(256, 2) void gemm_bf3_kernel(
    const bf16* __restrict__ Ahi_g, const bf16* __restrict__ Alo_g,
    const bf16* __restrict__ Bhi_g, const bf16* __restrict__ Blo_g,
    float* __restrict__ Cf, bf16* __restrict__ Chi, bf16* __restrict__ Clo,
    int M, int N, int K)
{
    extern __shared__ bf16 sm[];
    const uint32_t smb = smem_u32(sm);

    const int tid  = threadIdx.x;
    const int wid  = tid >> 5, lane = tid & 31;
    const int bm   = blockIdx.y * 128, bn = blockIdx.x * 128;
    const int wm   = (wid & 3) * 32;
    const int wn   = (wid >> 2) * 64;
    const int qr   = lane >> 2;
    const int qk   = lane & 3;

    const int t8 = lane >> 3, r8 = lane & 7;
    const int a_r = ((t8 & 1) << 3) + r8;
    const int a_c = (t8 >> 1) << 3;
    const int b_r = ((t8 >> 1) << 3) + r8;
    const int b_c = (t8 & 1) << 3;

    const int lr0 = tid >> 2;
    const int lq  = tid & 3;

    const bf16* gAh0 = Ahi_g + (size_t)(bm + lr0) * K + lq * 8;
    const bf16* gAl0 = Alo_g + (size_t)(bm + lr0) * K + lq * 8;
    const bf16* gBh0 = Bhi_g + (size_t)(bn + lr0) * K + lq * 8;
    const bf16* gBl0 = Blo_g + (size_t)(bn + lr0) * K + lq * 8;
    const size_t rstep = (size_t)64 * K;

    uint32_t sAh[2], sAl[2], sBh[2], sBl[2];
    #pragma unroll
    for (int b = 0; b < 2; b++) {
        const uint32_t base = smb + b * BUFB * 2;
        sAh[b] = base + (lr0 * SSTB + lq * 8) * 2;
        sAl[b] = sAh[b] + OPB * 2;
        sBh[b] = sAl[b] + OPB * 2;
        sBl[b] = sBh[b] + OPB * 2;
    }
    const uint32_t sstep = 64 * SSTB * 2;

    float acc[2][8][4];
    #pragma unroll
    for (int mt = 0; mt < 2; mt++)
        #pragma unroll
        for (int nt = 0; nt < 8; nt++)
            #pragma unroll
            for (int v = 0; v < 4; v++) acc[mt][nt][v] = 0.f;

    const int NT = K / 32;

    CP_ASYNC16(sAh[0], gAh0);  CP_ASYNC16(sAh[0] + sstep, gAh0 + rstep);
    CP_ASYNC16(sAl[0], gAl0);  CP_ASYNC16(sAl[0] + sstep, gAl0 + rstep);
    CP_ASYNC16(sBh[0], gBh0);  CP_ASYNC16(sBh[0] + sstep, gBh0 + rstep);
    CP_ASYNC16(sBl[0], gBl0);  CP_ASYNC16(sBl[0] + sstep, gBl0 + rstep);
    CP_COMMIT();

    for (int kt = 0; kt < NT; kt++) {
        const int buf = kt & 1;
        if (kt + 1 < NT) {
            const int nb = buf ^ 1;
            const int off = (kt + 1) * 32;
            CP_ASYNC16(sAh[nb], gAh0 + off);  CP_ASYNC16(sAh[nb] + sstep, gAh0 + rstep + off);
            CP_ASYNC16(sAl[nb], gAl0 + off);  CP_ASYNC16(sAl[nb] + sstep, gAl0 + rstep + off);
            CP_ASYNC16(sBh[nb], gBh0 + off);  CP_ASYNC16(sBh[nb] + sstep, gBh0 + rstep + off);
            CP_ASYNC16(sBl[nb], gBl0 + off);  CP_ASYNC16(sBl[nb] + sstep, gBl0 + rstep + off);
            CP_COMMIT();
            CP_WAIT(1);
        } else {
            CP_WAIT(0);
        }
        __syncthreads();

        const uint32_t bAh = smb + buf * BUFB * 2;
        const uint32_t bAl = bAh + OPB * 2;
        const uint32_t bBh = bAl + OPB * 2;
        const uint32_t bBl = bBh + OPB * 2;

        #pragma unroll
        for (int ks = 0; ks < 2; ks++) {
            const int k0 = ks * 16;
            uint32_t afh[2][4], afl[2][4];
            #pragma unroll
            for (int mt = 0; mt < 2; mt++) {
                const uint32_t aoff = ((wm + mt * 16 + a_r) * SSTB + k0 + a_c) * 2;
                ldsm4(afh[mt], bAh + aoff);
                ldsm4(afl[mt], bAl + aoff);
            }
            #pragma unroll
            for (int p = 0; p < 4; p++) {
                const uint32_t boff = ((wn + p * 16 + b_r) * SSTB + k0 + b_c) * 2;
                uint32_t bh4[4], bl4[4];
                ldsm4(bh4, bBh + boff);
                ldsm4(bl4, bBl + boff);
                #pragma unroll
                for (int mt = 0; mt < 2; mt++) {
                    mma_bf16(acc[mt][2 * p],     afh[mt], bh4);
                    mma_bf16(acc[mt][2 * p + 1], afh[mt], bh4 + 2);
                }
                #pragma unroll
                for (int mt = 0; mt < 2; mt++) {
                    mma_bf16(acc[mt][2 * p],     afh[mt], bl4);
                    mma_bf16(acc[mt][2 * p + 1], afh[mt], bl4 + 2);
                }
                #pragma unroll
                for (int mt = 0; mt < 2; mt++) {
                    mma_bf16(acc[mt][2 * p],     afl[mt], bh4);
                    mma_bf16(acc[mt][2 * p + 1], afl[mt], bh4 + 2);
                }
            }
        }
        __syncthreads();
    }

    #pragma unroll
    for (int mt = 0; mt < 2; mt++) {
        const int r = bm + wm + mt * 16 + qr;
        #pragma unroll
        for (int nt = 0; nt < 8; nt++) {
            const int ncol = bn + wn + nt * 8 + 2 * qk;
            float sc = 1.f;
            if (QSCALE && ncol < HD) sc = 0.125f;   // fold 1/sqrt(D) into Q
            if (SPLIT_OUT) {
                uint32_t h, l;
                split2(acc[mt][nt][0] * sc, acc[mt][nt][1] * sc, h, l);
                *(uint32_t*)(Chi + (size_t)r * N + ncol) = h;
                *(uint32_t*)(Clo + (size_t)r * N + ncol) = l;
                split2(acc[mt][nt][2] * sc, acc[mt][nt][3] * sc, h, l);
                *(uint32_t*)(Chi + (size_t)(r + 8) * N + ncol) = h;
                *(uint32_t*)(Clo + (size_t)(r + 8) * N + ncol) = l;
            } else {
                *(float2*)(Cf + (size_t)r * N + ncol) =
                    make_float2(acc[mt][nt][0], acc[mt][nt][1]);
                *(float2*)(Cf + (size_t)(r + 8) * N + ncol) =
                    make_float2(acc[mt][nt][2], acc[mt][nt][3]);
            }
        }
    }
}

// ---------------------------------------------------------------------------
// Flash attention (R8 structure) with __launch_bounds__(256,2) for 2 CTAs/SM.
// Q is pre-scaled by 0.125 (done in QKV epilogue) -> no scale loop here.
// ---------------------------------------------------------------------------
#define AST 72
#define ATILE (64 * AST)
#define ASTAGE (4 * ATILE)
#define ATTN_SMEM (2 * ASTAGE * 2)

__global__ __launch_bounds__(256, 2) void attn_mma_kernel(
    const bf16* __restrict__ qh, const bf16* __restrict__ ql,
    bf16* __restrict__ ah, bf16* __restrict__ al)
{
    extern __shared__ bf16 asmem[];
    const uint32_t smb = smem_u32(asmem);

    const int tid = threadIdx.x, wid = tid >> 5, lane = tid & 31;
    const int qr = lane >> 2, qk = lane & 3;
    const int qb = (int)gridDim.y - 1 - (int)blockIdx.y;   // LPT
    const int bh = blockIdx.x;
    const int b = bh >> 4, h = bh & 15;

    const size_t seq0 = (size_t)b * C_SZ;
    const int wr = qb * 128 + wid * 16;

    const int t8 = lane >> 3, r8 = lane & 7;
    const int kb_r = ((t8 >> 1) << 3) + r8;
    const int kb_c = (t8 & 1) << 3;
    const int vb_r = ((t8 & 1) << 3) + r8;
    const int vb_c = (t8 >> 1) << 3;

    const int kr0 = tid >> 3;
    const int kq  = tid & 7;
    const uint32_t lsoff = (kr0 * AST + kq * 8) * 2;
    const uint32_t kstep = 32 * AST * 2;

    uint32_t qhi[4][4], qlo[4][4];
    {
        const bf16* qb0 = qh + (seq0 + wr) * F3 + h * D_SZ;
        const bf16* qb1 = ql + (seq0 + wr) * F3 + h * D_SZ;
        #pragma unroll
        for (int kc = 0; kc < 4; kc++) {
            const int d0 = kc * 16 + 2 * qk;
            qhi[kc][0] = *(const uint32_t*)(qb0 + (size_t)qr * F3 + d0);
            qhi[kc][1] = *(const uint32_t*)(qb0 + (size_t)(qr + 8) * F3 + d0);
            qhi[kc][2] = *(const uint32_t*)(qb0 + (size_t)qr * F3 + d0 + 8);
            qhi[kc][3] = *(const uint32_t*)(qb0 + (size_t)(qr + 8) * F3 + d0 + 8);
            qlo[kc][0] = *(const uint32_t*)(qb1 + (size_t)qr * F3 + d0);
            qlo[kc][1] = *(const uint32_t*)(qb1 + (size_t)(qr + 8) * F3 + d0);
            qlo[kc][2] = *(const uint32_t*)(qb1 + (size_t)qr * F3 + d0 + 8);
            qlo[kc][3] = *(const uint32_t*)(qb1 + (size_t)(qr + 8) * F3 + d0 + 8);
        }
    }

    float m0 = -1e30f, m1 = -1e30f, l0 = 0.f, l1 = 0.f;
    float o[8][4];
    #pragma unroll
    for (int nt = 0; nt < 8; nt++)
        #pragma unroll
        for (int v = 0; v < 4; v++) o[nt][v] = 0.f;

    const int nkv = 2 * qb + 2;

    auto issue_tile = [&](int kb, int s) {
        const uint32_t sb = smb + s * ASTAGE * 2;
        const uint32_t uKh = sb,                 uKl = sb + ATILE * 2;
        const uint32_t uVh = sb + 2 * ATILE * 2, uVl = sb + 3 * ATILE * 2;
        const size_t krow0 = (seq0 + kb * 64 + kr0) * F3;
        const size_t kr32 = (size_t)32 * F3;
        const bf16* gKh = qh + krow0 + HD + h * D_SZ + kq * 8;
        const bf16* gKl = ql + krow0 + HD + h * D_SZ + kq * 8;
        const bf16* gVh = qh + krow0 + 2 * HD + h * D_SZ + kq * 8;
        const bf16* gVl = ql + krow0 + 2 * HD + h * D_SZ + kq * 8;
        CP_ASYNC16(uKh + lsoff, gKh);  CP_ASYNC16(uKh + lsoff + kstep, gKh + kr32);
        CP_ASYNC16(uKl + lsoff, gKl);  CP_ASYNC16(uKl + lsoff + kstep, gKl + kr32);
        CP_ASYNC16(uVh + lsoff, gVh);  CP_ASYNC16(uVh + lsoff + kstep, gVh + kr32);
        CP_ASYNC16(uVl + lsoff, gVl);  CP_ASYNC16(uVl + lsoff + kstep, gVl + kr32);
        CP_COMMIT();
    };

    issue_tile(0, 0);

    for (int kb = 0; kb < nkv; kb++) {
        CP_WAIT(0);
        __syncthreads();

        if (kb + 1 < nkv) issue_tile(kb + 1, (kb + 1) & 1);

        if (kb * 64 <= wr + 15) {
            const uint32_t sb = smb + (kb & 1) * ASTAGE * 2;
            const uint32_t uKhi = sb,                 uKlo = sb + ATILE * 2;
            const uint32_t uVhi = sb + 2 * ATILE * 2, uVlo = sb + 3 * ATILE * 2;

            float s[8][4];
            #pragma unroll
            for (int nt = 0; nt < 8; nt++)
                #pragma unroll
                for (int v = 0; v < 4; v++) s[nt][v] = 0.f;

            #pragma unroll
            for (int kc = 0; kc < 4; kc++) {
                const int k0 = kc * 16;
                #pragma unroll
                for (int p = 0; p < 4; p++) {
                    const uint32_t boff = ((p * 16 + kb_r) * AST + k0 + kb_c) * 2;
                    uint32_t bh4[4], bl4[4];
                    ldsm4(bh4, uKhi + boff);
                    ldsm4(bl4, uKlo + boff);
                    mma_bf16(s[2 * p],     qhi[kc], bh4);
                    mma_bf16(s[2 * p + 1], qhi[kc], bh4 + 2);
                    mma_bf16(s[2 * p],     qhi[kc], bl4);
                    mma_bf16(s[2 * p + 1], qhi[kc], bl4 + 2);
                    mma_bf16(s[2 * p],     qlo[kc], bh4);
                    mma_bf16(s[2 * p + 1], qlo[kc], bh4 + 2);
                }
            }

            // causal mask only (scale pre-folded into Q)
            if (kb * 64 + 63 > wr) {
                #pragma unroll
                for (int nt = 0; nt < 8; nt++) {
                    const int colb = kb * 64 + nt * 8 + 2 * qk;
                    const int r0 = wr + qr, r1 = r0 + 8;
                    if (colb > r0)     s[nt][0] = -1e30f;
                    if (colb + 1 > r0) s[nt][1] = -1e30f;
                    if (colb > r1)     s[nt][2] = -1e30f;
                    if (colb + 1 > r1) s[nt][3] = -1e30f;
                }
            }

            {
                float mx0 = -1e30f, mx1 = -1e30f;
                #pragma unroll
                for (int nt = 0; nt < 8; nt++) {
                    mx0 = fmaxf(mx0, fmaxf(s[nt][0], s[nt][1]));
                    mx1 = fmaxf(mx1, fmaxf(s[nt][2], s[nt][3]));
                }
                mx0 = fmaxf(mx0, __shfl_xor_sync(0xffffffffu, mx0, 1));
                mx0 = fmaxf(mx0, __shfl_xor_sync(0xffffffffu, mx0, 2));
                mx1 = fmaxf(mx1, __shfl_xor_sync(0xffffffffu, mx1, 1));
                mx1 = fmaxf(mx1, __shfl_xor_sync(0xffffffffu, mx1, 2));

                const float mn0 = fmaxf(m0, mx0), mn1 = fmaxf(m1, mx1);
                const float a0 = __expf(m0 - mn0), a1 = __expf(m1 - mn1);
                float s0 = 0.f, s1 = 0.f;
                #pragma unroll
                for (int nt = 0; nt < 8; nt++) {
                    s[nt][0] = __expf(s[nt][0] - mn0);
                    s[nt][1] = __expf(s[nt][1] - mn0);
                    s[nt][2] = __expf(s[nt][2] - mn1);
                    s[nt][3] = __expf(s[nt][3] - mn1);
                    s0 += s[nt][0] + s[nt][1];
                    s1 += s[nt][2] + s[nt][3];
                }
                s0 += __shfl_xor_sync(0xffffffffu, s0, 1);
                s0 += __shfl_xor_sync(0xffffffffu, s0, 2);
                s1 += __shfl_xor_sync(0xffffffffu, s1, 1);
                s1 += __shfl_xor_sync(0xffffffffu, s1, 2);
                l0 = l0 * a0 + s0;  m0 = mn0;
                l1 = l1 * a1 + s1;  m1 = mn1;
                #pragma unroll
                for (int nt = 0; nt < 8; nt++) {
                    o[nt][0] *= a0; o[nt][1] *= a0;
                    o[nt][2] *= a1; o[nt][3] *= a1;
                }
            }

            #pragma unroll
            for (int kc = 0; kc < 4; kc++) {
                uint32_t ph[4], pl[4];
                split2(s[2 * kc][0],     s[2 * kc][1],     ph[0], pl[0]);
                split2(s[2 * kc][2],     s[2 * kc][3],     ph[1], pl[1]);
                split2(s[2 * kc + 1][0], s[2 * kc + 1][1], ph[2], pl[2]);
                split2(s[2 * kc + 1][2], s[2 * kc + 1][3], ph[3], pl[3]);
                #pragma unroll
                for (int p = 0; p < 4; p++) {
                    const uint32_t voff = ((kc * 16 + vb_r) * AST + p * 16 + vb_c) * 2;
                    uint32_t bh4[4], bl4[4];
                    ldsm4t(bh4, uVhi + voff);
                    ldsm4t(bl4, uVlo + voff);
                    mma_bf16(o[2 * p],     ph, bh4);
                    mma_bf16(o[2 * p + 1], ph, bh4 + 2);
                    mma_bf16(o[2 * p],     ph, bl4);
                    mma_bf16(o[2 * p + 1], ph, bl4 + 2);
                    mma_bf16(o[2 * p],     pl, bh4);
                    mma_bf16(o[2 * p + 1], pl, bh4 + 2);
                }
            }
        }
    }

    const float i0 = 1.f / l0, i1 = 1.f / l1;
    #pragma unroll
    for (int nt = 0; nt < 8; nt++) {
        const int col = h * D_SZ + nt * 8 + 2 * qk;
        const size_t r0 = seq0 + wr + qr, r1 = r0 + 8;
        uint32_t hh, ll;
        split2(o[nt][0] * i0, o[nt][1] * i0, hh, ll);
        *(uint32_t*)(ah + r0 * HD + col) = hh;
        *(uint32_t*)(al + r0 * HD + col) = ll;
        split2(o[nt][2] * i1, o[nt][3] * i1, hh, ll);
        *(uint32_t*)(ah + r1 * HD + col) = hh;
        *(uint32_t*)(al + r1 * HD + col) = ll;
    }
}

// ---------------------------------------------------------------------------
extern "C" void kernel_launch(void* const* d_in, const int* in_sizes, int n_in,
                              void* d_out, int out_size)
{
    const float* x     = (const float*)d_in[0];
    const float* w_qkv = (const float*)d_in[1];
    const float* w_out = (const float*)d_in[2];
    float* out = (float*)d_out;

    bf16 *xh, *xl, *wqh, *wql, *woh, *wol, *qh, *ql, *ahp, *alp;
    cudaGetSymbolAddress((void**)&xh,  g_xh);  cudaGetSymbolAddress((void**)&xl,  g_xl);
    cudaGetSymbolAddress((void**)&wqh, g_wqh); cudaGetSymbolAddress((void**)&wql, g_wql);
    cudaGetSymbolAddress((void**)&woh, g_woh); cudaGetSymbolAddress((void**)&wol, g_wol);
    cudaGetSymbolAddress((void**)&qh,  g_qh);  cudaGetSymbolAddress((void**)&ql,  g_ql);
    cudaGetSymbolAddress((void**)&ahp, g_ah);  cudaGetSymbolAddress((void**)&alp, g_al);

    cudaFuncSetAttribute((const void*)gemm_bf3_kernel<true, true>,
                         cudaFuncAttributeMaxDynamicSharedMemorySize, GEMM_SMEM);
    cudaFuncSetAttribute((const void*)gemm_bf3_kernel<false, false>,
                         cudaFuncAttributeMaxDynamicSharedMemorySize, GEMM_SMEM);
    cudaFuncSetAttribute(attn_mma_kernel,
                         cudaFuncAttributeMaxDynamicSharedMemorySize, ATTN_SMEM);

    // 0) split inputs once
    {
        int n4 = (M_SZ * E_SZ) / 4;
        split_kernel<<<(n4 + 255) / 256, 256>>>(x, xh, xl, n4);
        n4 = (F3 * E_SZ) / 4;
        split_kernel<<<(n4 + 255) / 256, 256>>>(w_qkv, wqh, wql, n4);
        n4 = (E_SZ * HD) / 4;
        split_kernel<<<(n4 + 255) / 256, 256>>>(w_out, woh, wol, n4);
    }

    // 1) QKV projection -> split bf16 qkv (Q columns pre-scaled by 0.125)
    {
        dim3 grid(F3 / 128, M_SZ / 128);
        gemm_bf3_kernel<true, true><<<grid, 256, GEMM_SMEM>>>(
            xh, xl, wqh, wql, nullptr, qh, ql, M_SZ, F3, E_SZ);
    }

    // 2) causal flash attention -> split bf16 attn
    {
        dim3 grid(B_SZ * H_SZ, C_SZ / 128);
        attn_mma_kernel<<<grid, 256, ATTN_SMEM>>>(qh, ql, ahp, alp);
    }

    // 3) output projection -> fp32 out
    {
        dim3 grid(E_SZ / 128, M_SZ / 128);
        gemm_bf3_kernel<false, false><<<grid, 256, GEMM_SMEM>>>(
            ahp, alp, woh, wol, out, nullptr, nullptr, M_SZ, E_SZ, HD);
    }
}